// round 2
// baseline (speedup 1.0000x reference)
#include <cuda_runtime.h>
#include <math.h>

// Problem constants
#define Bb 2
#define Ss 4096
#define Hh 2048
#define D2c 1024
#define SCALE 0.125f   // 1/sqrt(64)

// ---------------- static device scratch (allocation-free rule) --------------
__device__ float g_q  [(long long)Bb*Ss*Hh];   // 64 MB
__device__ float g_qr [(long long)Bb*Ss*Hh];   // 64 MB
__device__ float g_k  [(long long)Bb*Ss*Hh];   // 64 MB
__device__ float g_p  [(long long)Bb*Ss*Ss];   // 128 MB (scores/probs)
__device__ float g_ctx[(long long)Bb*Ss*Hh];   // 64 MB

// ---------------- fp32 SGEMM: C = alpha * A @ op(B) -------------------------
// TRANSB=true : B is [N,K] row-major (C = A * B^T)  -- NT
// TRANSB=false: B is [K,N] row-major (C = A * B)    -- NN
// Tile 128x128x8, 256 threads, 8x8 per thread. All dims multiples of 128/8.
template<bool TRANSB>
__global__ void __launch_bounds__(256)
sgemm_kernel(const float* __restrict__ A, const float* __restrict__ B,
             float* __restrict__ C, int M, int N, int K,
             long long strideA, long long strideB, long long strideC,
             float alpha)
{
    A += (long long)blockIdx.z * strideA;
    B += (long long)blockIdx.z * strideB;
    C += (long long)blockIdx.z * strideC;

    __shared__ float As[8][128];
    __shared__ float Bs[8][128];

    const int tid = threadIdx.x;                 // 0..255
    const long long bm = (long long)blockIdx.y * 128;
    const long long bn = (long long)blockIdx.x * 128;

    // loader indices: 128 rows x 8 k, one float4 per thread
    const int l_row = tid >> 1;                  // 0..127
    const int l_k4  = (tid & 1) * 4;             // 0 or 4
    // NN B loader: 8 k-rows x 128 n, one float4 per thread
    const int bn_k  = tid >> 5;                  // 0..7
    const int bn_n  = (tid & 31) * 4;            // 0..124

    const int ty = tid >> 4;                     // 0..15 -> C rows
    const int tx = tid & 15;                     // 0..15 -> C cols

    float acc[8][8];
    #pragma unroll
    for (int i = 0; i < 8; ++i)
        #pragma unroll
        for (int j = 0; j < 8; ++j) acc[i][j] = 0.f;

    for (int k0 = 0; k0 < K; k0 += 8) {
        // A tile (transpose into [k][m])
        float4 av = *(const float4*)&A[(bm + l_row) * (long long)K + k0 + l_k4];
        As[l_k4+0][l_row] = av.x;
        As[l_k4+1][l_row] = av.y;
        As[l_k4+2][l_row] = av.z;
        As[l_k4+3][l_row] = av.w;
        if (TRANSB) {
            float4 bv = *(const float4*)&B[(bn + l_row) * (long long)K + k0 + l_k4];
            Bs[l_k4+0][l_row] = bv.x;
            Bs[l_k4+1][l_row] = bv.y;
            Bs[l_k4+2][l_row] = bv.z;
            Bs[l_k4+3][l_row] = bv.w;
        } else {
            float4 bv = *(const float4*)&B[(long long)(k0 + bn_k) * N + bn + bn_n];
            *(float4*)&Bs[bn_k][bn_n] = bv;
        }
        __syncthreads();

        #pragma unroll
        for (int k = 0; k < 8; ++k) {
            float4 a0 = *(const float4*)&As[k][ty * 8];
            float4 a1 = *(const float4*)&As[k][ty * 8 + 4];
            float4 b0 = *(const float4*)&Bs[k][tx * 8];
            float4 b1 = *(const float4*)&Bs[k][tx * 8 + 4];
            float ra[8] = {a0.x,a0.y,a0.z,a0.w,a1.x,a1.y,a1.z,a1.w};
            float rb[8] = {b0.x,b0.y,b0.z,b0.w,b1.x,b1.y,b1.z,b1.w};
            #pragma unroll
            for (int i = 0; i < 8; ++i)
                #pragma unroll
                for (int j = 0; j < 8; ++j)
                    acc[i][j] = fmaf(ra[i], rb[j], acc[i][j]);
        }
        __syncthreads();
    }

    #pragma unroll
    for (int i = 0; i < 8; ++i) {
        long long crow = (bm + ty * 8 + i) * (long long)N + bn + tx * 8;
        float4 v0 = make_float4(acc[i][0]*alpha, acc[i][1]*alpha,
                                acc[i][2]*alpha, acc[i][3]*alpha);
        float4 v1 = make_float4(acc[i][4]*alpha, acc[i][5]*alpha,
                                acc[i][6]*alpha, acc[i][7]*alpha);
        *(float4*)&C[crow]     = v0;
        *(float4*)&C[crow + 4] = v1;
    }
}

// ---------------- RoPE: interleaved rotate over full H ----------------------
// position_ids is arange(S) in this problem, so pos[s] == s; index tables by s
// directly (avoids int32-vs-int64 dtype hazard on the position buffer).
// out[..., 2i]   = x[i]*cos - x[i+D2]*sin
// out[..., 2i+1] = x[i]*sin + x[i+D2]*cos
__global__ void __launch_bounds__(256)
rope_kernel(const float* __restrict__ x, float* __restrict__ out,
            const float* __restrict__ cosb, const float* __restrict__ sinb)
{
    long long idx = (long long)blockIdx.x * blockDim.x + threadIdx.x; // B*S*D2
    int i = (int)(idx & (D2c - 1));
    long long bs = idx >> 10;            // idx / D2
    int s = (int)(bs & (Ss - 1));
    long long base = bs * Hh;
    float c  = cosb[(long long)s * D2c + i];
    float sn = sinb[(long long)s * D2c + i];
    float xr = x[base + i];
    float xi = x[base + D2c + i];
    out[base + 2*i]     = xr * c  - xi * sn;
    out[base + 2*i + 1] = xr * sn + xi * c;
}

// ---------------- row softmax (in place), row length = Ss -------------------
__global__ void __launch_bounds__(256)
softmax_kernel(float* __restrict__ P)
{
    float* row = P + (long long)blockIdx.x * Ss;
    const int tid = threadIdx.x;
    __shared__ float red[256];

    float m = -INFINITY;
    for (int j = tid; j < Ss; j += 256) m = fmaxf(m, row[j]);
    red[tid] = m; __syncthreads();
    for (int s = 128; s > 0; s >>= 1) {
        if (tid < s) red[tid] = fmaxf(red[tid], red[tid + s]);
        __syncthreads();
    }
    m = red[0]; __syncthreads();

    float sum = 0.f;
    for (int j = tid; j < Ss; j += 256) {
        float e = expf(row[j] - m);
        row[j] = e;
        sum += e;
    }
    red[tid] = sum; __syncthreads();
    for (int s = 128; s > 0; s >>= 1) {
        if (tid < s) red[tid] += red[tid + s];
        __syncthreads();
    }
    float inv = 1.f / red[0];
    for (int j = tid; j < Ss; j += 256) row[j] *= inv;
}

// ---------------- launch ----------------------------------------------------
extern "C" void kernel_launch(void* const* d_in, const int* in_sizes, int n_in,
                              void* d_out, int out_size)
{
    const float* hs   = (const float*)d_in[0];
    const float* wq   = (const float*)d_in[1];
    const float* wk   = (const float*)d_in[2];
    const float* wv   = (const float*)d_in[3];
    const float* wo   = (const float*)d_in[4];
    const float* fcos = (const float*)d_in[5];
    const float* fsin = (const float*)d_in[6];
    // d_in[7] = position_ids (== arange(S)); unused by construction.

    float* out   = (float*)d_out;
    const long long T = (long long)Bb * Ss * Hh;     // 16,777,216
    float* out_o = out;
    float* out_k = out + T;
    float* out_v = out + 2 * T;

    float *q, *qr, *k, *p, *ctx;
    cudaGetSymbolAddress((void**)&q,   g_q);
    cudaGetSymbolAddress((void**)&qr,  g_qr);
    cudaGetSymbolAddress((void**)&k,   g_k);
    cudaGetSymbolAddress((void**)&p,   g_p);
    cudaGetSymbolAddress((void**)&ctx, g_ctx);

    const int M  = Bb * Ss;   // 8192
    const int N  = Hh;        // 2048
    const int Kd = Hh;        // 2048

    dim3 blk(256);
    dim3 gproj(N / 128, M / 128, 1);                  // 16 x 64

    // projections: q/k -> scratch, v -> out directly (NT: W is [N,K])
    sgemm_kernel<true><<<gproj, blk>>>(hs, wq, q,     M, N, Kd, 0, 0, 0, 1.f);
    sgemm_kernel<true><<<gproj, blk>>>(hs, wk, k,     M, N, Kd, 0, 0, 0, 1.f);
    sgemm_kernel<true><<<gproj, blk>>>(hs, wv, out_v, M, N, Kd, 0, 0, 0, 1.f);

    // RoPE: q -> qr (scratch), k -> out_k (final output #2)
    long long nrope = (long long)Bb * Ss * D2c;       // 8,388,608
    dim3 grope((unsigned)(nrope / 256));
    rope_kernel<<<grope, blk>>>(q, qr,    fcos, fsin);
    rope_kernel<<<grope, blk>>>(k, out_k, fcos, fsin);

    // scores = SCALE * Qr @ Kr^T, per batch (NT)
    dim3 gscore(Ss / 128, Ss / 128, Bb);              // 32 x 32 x 2
    sgemm_kernel<true><<<gscore, blk>>>(qr, out_k, p, Ss, Ss, Hh,
                                        (long long)Ss*Hh, (long long)Ss*Hh,
                                        (long long)Ss*Ss, SCALE);

    // softmax rows (in place)
    softmax_kernel<<<Bb * Ss, blk>>>(p);

    // ctx = P @ V, per batch (NN: V is [K,N])
    dim3 gctx(Hh / 128, Ss / 128, Bb);                // 16 x 32 x 2
    sgemm_kernel<false><<<gctx, blk>>>(p, out_v, ctx, Ss, Hh, Ss,
                                       (long long)Ss*Ss, (long long)Ss*Hh,
                                       (long long)Ss*Hh, 1.f);

    // output = ctx @ Wo^T (both batches fused: M=8192) -> out_o
    sgemm_kernel<true><<<gproj, blk>>>(ctx, wo, out_o, M, N, Kd, 0, 0, 0, 1.f);
}

// round 4
// speedup vs baseline: 1.9338x; 1.9338x over previous
#include <cuda_runtime.h>
#include <cuda_bf16.h>
#include <math.h>
#include <stdint.h>

#define Bb 2
#define Ss 4096
#define Hh 2048
#define D2c 1024
#define SCALEF 0.125f

// ---------------- static device scratch (allocation-free rule) --------------
__device__ __align__(256) float g_q  [(size_t)Bb*Ss*Hh];
__device__ __align__(256) float g_k  [(size_t)Bb*Ss*Hh];
__device__ __align__(256) float g_p  [(size_t)Bb*Ss*Ss];
__device__ __align__(256) float g_ctx[(size_t)Bb*Ss*Hh];
__device__ __align__(256) __nv_bfloat16 g_hs2 [(size_t)Bb*Ss*2*Hh];
__device__ __align__(256) __nv_bfloat16 g_wq2 [(size_t)Hh*2*Hh];
__device__ __align__(256) __nv_bfloat16 g_wk2 [(size_t)Hh*2*Hh];
__device__ __align__(256) __nv_bfloat16 g_wv2 [(size_t)Hh*2*Hh];
__device__ __align__(256) __nv_bfloat16 g_wo2 [(size_t)Hh*2*Hh];
__device__ __align__(256) __nv_bfloat16 g_qr2 [(size_t)Bb*Ss*2*Hh];
__device__ __align__(256) __nv_bfloat16 g_kr2 [(size_t)Bb*Ss*2*Hh];
__device__ __align__(256) __nv_bfloat16 g_p2  [(size_t)Bb*Ss*2*Ss];
__device__ __align__(256) __nv_bfloat16 g_vt2 [(size_t)Bb*Hh*2*Ss];
__device__ __align__(256) __nv_bfloat16 g_ctx2[(size_t)Bb*Ss*2*Hh];

// ---------------- PTX helpers (portable: sm_80+ only) -----------------------
__device__ __forceinline__ uint32_t smem_u32(const void* p) {
    uint32_t a;
    asm("{ .reg .u64 t; cvta.to.shared.u64 t, %1; cvt.u32.u64 %0, t; }" : "=r"(a) : "l"(p));
    return a;
}
__device__ __forceinline__ void cp_async16(uint32_t dst, const void* src) {
    asm volatile("cp.async.cg.shared.global [%0], [%1], 16;" :: "r"(dst), "l"(src) : "memory");
}
#define CP_COMMIT() asm volatile("cp.async.commit_group;" ::: "memory")
#define CP_WAIT1()  asm volatile("cp.async.wait_group 1;" ::: "memory")
#define CP_WAIT0()  asm volatile("cp.async.wait_group 0;" ::: "memory")

__device__ __forceinline__ void ldsm_x4(uint32_t& r0, uint32_t& r1, uint32_t& r2, uint32_t& r3,
                                        uint32_t addr) {
    asm volatile("ldmatrix.sync.aligned.m8n8.x4.shared.b16 {%0,%1,%2,%3}, [%4];"
                 : "=r"(r0), "=r"(r1), "=r"(r2), "=r"(r3) : "r"(addr));
}
__device__ __forceinline__ void mma16816(float& d0, float& d1, float& d2, float& d3,
                                         uint32_t a0, uint32_t a1, uint32_t a2, uint32_t a3,
                                         uint32_t b0, uint32_t b1) {
    asm volatile("mma.sync.aligned.m16n8k16.row.col.f32.bf16.bf16.f32 "
                 "{%0,%1,%2,%3}, {%4,%5,%6,%7}, {%8,%9}, {%0,%1,%2,%3};"
                 : "+f"(d0), "+f"(d1), "+f"(d2), "+f"(d3)
                 : "r"(a0), "r"(a1), "r"(a2), "r"(a3), "r"(b0), "r"(b1));
}
__device__ __forceinline__ uint32_t swz(uint32_t b) { return b ^ ((b >> 3) & 0x70); }

// ---------------- mma.sync bf16 3-pass GEMM ---------------------------------
// C[m][n] = alpha * sum over 3 passes: Ahi*Bhi + Alo*Bhi + Ahi*Blo
// A2: [M x 2K] bf16 row-major (hi cols [0,K), lo [K,2K)). B2: [N x 2K] same.
#define BM 128
#define BN 128
#define BK 64
#define STAGES 3
#define ATILE (BM * BK * 2)          // 16384 B
#define STAGE_BYTES (2 * ATILE)      // 32768 B
#define GSMEM (STAGES * STAGE_BYTES) // 98304 B

__device__ __forceinline__ void load_chunk(
    const __nv_bfloat16* __restrict__ A2, const __nv_bfloat16* __restrict__ B2,
    uint32_t sb, int c, int kchunks, int K, long long K2, int m0, int n0, int tid)
{
    int pass = c / kchunks;
    int kk = c - pass * kchunks;
    int aoff = kk * BK + (pass == 1 ? K : 0);
    int boff = kk * BK + (pass == 2 ? K : 0);
    uint32_t bufA = sb + (uint32_t)(c % STAGES) * STAGE_BYTES;
    uint32_t bufB = bufA + ATILE;
    #pragma unroll
    for (int j = 0; j < 4; ++j) {
        int lin = tid + j * 256;
        int row = lin >> 3, ch = lin & 7;
        cp_async16(bufA + swz(row * 128 + ch * 16),
                   A2 + (long long)(m0 + row) * K2 + aoff + ch * 8);
    }
    #pragma unroll
    for (int j = 0; j < 4; ++j) {
        int lin = tid + j * 256;
        int row = lin >> 3, ch = lin & 7;
        cp_async16(bufB + swz(row * 128 + ch * 16),
                   B2 + (long long)(n0 + row) * K2 + boff + ch * 8);
    }
}

__global__ void __launch_bounds__(256, 2)
gemm3p(const __nv_bfloat16* __restrict__ A2, const __nv_bfloat16* __restrict__ B2,
       float* __restrict__ C, int M, int N, int K,
       long long sA, long long sB, long long sC, float alpha)
{
    extern __shared__ char smem[];
    uint32_t sb = smem_u32(smem);
    const int tid = threadIdx.x;
    const int wid = tid >> 5, lane = tid & 31;
    const int wm = wid & 1;      // 2 warps along M: 64 rows each
    const int wn = wid >> 1;     // 4 warps along N: 32 cols each
    A2 += (long long)blockIdx.z * sA;
    B2 += (long long)blockIdx.z * sB;
    C  += (long long)blockIdx.z * sC;
    const int m0 = blockIdx.y * BM, n0 = blockIdx.x * BN;
    const long long K2 = 2LL * K;
    const int kchunks = K / BK, nchunks = 3 * kchunks;

    float acc[4][4][4];
    #pragma unroll
    for (int i = 0; i < 4; ++i)
        #pragma unroll
        for (int j = 0; j < 4; ++j)
            #pragma unroll
            for (int q = 0; q < 4; ++q) acc[i][j][q] = 0.f;

    // ldmatrix lane addressing: row = base + (lane&15), k-half = lane>>4
    const int lrow = lane & 15;
    const int lhalf = lane >> 4;

    load_chunk(A2, B2, sb, 0, kchunks, K, K2, m0, n0, tid); CP_COMMIT();
    load_chunk(A2, B2, sb, 1, kchunks, K, K2, m0, n0, tid); CP_COMMIT();

    for (int c = 0; c < nchunks; ++c) {
        if (c + 1 < nchunks) { CP_WAIT1(); } else { CP_WAIT0(); }
        __syncthreads();
        if (c + 2 < nchunks) {
            load_chunk(A2, B2, sb, c + 2, kchunks, K, K2, m0, n0, tid);
            CP_COMMIT();
        }
        uint32_t aBase = sb + (uint32_t)(c % STAGES) * STAGE_BYTES;
        uint32_t bBase = aBase + ATILE;
        #pragma unroll
        for (int ks = 0; ks < BK / 16; ++ks) {
            uint32_t a[4][4], b[4][2];
            int ch = ks * 2 + lhalf;
            #pragma unroll
            for (int im = 0; im < 4; ++im) {
                int row = wm * 64 + im * 16 + lrow;
                ldsm_x4(a[im][0], a[im][1], a[im][2], a[im][3],
                        aBase + row * 128 + ((ch ^ (row & 7)) * 16));
            }
            #pragma unroll
            for (int ib = 0; ib < 2; ++ib) {
                int row = wn * 32 + ib * 16 + lrow;
                ldsm_x4(b[2*ib][0], b[2*ib+1][0], b[2*ib][1], b[2*ib+1][1],
                        bBase + row * 128 + ((ch ^ (row & 7)) * 16));
            }
            #pragma unroll
            for (int im = 0; im < 4; ++im)
                #pragma unroll
                for (int in = 0; in < 4; ++in)
                    mma16816(acc[im][in][0], acc[im][in][1], acc[im][in][2], acc[im][in][3],
                             a[im][0], a[im][1], a[im][2], a[im][3],
                             b[in][0], b[in][1]);
        }
    }
    __syncthreads();

    // epilogue: thread holds (row0,col),(row0,col+1),(row0+8,col),(row0+8,col+1)
    const int r0 = lane >> 2;
    const int cc = (lane & 3) * 2;
    #pragma unroll
    for (int im = 0; im < 4; ++im) {
        #pragma unroll
        for (int in = 0; in < 4; ++in) {
            long long m = m0 + wm * 64 + im * 16 + r0;
            long long n = n0 + wn * 32 + in * 8 + cc;
            float2 v0 = make_float2(acc[im][in][0] * alpha, acc[im][in][1] * alpha);
            float2 v1 = make_float2(acc[im][in][2] * alpha, acc[im][in][3] * alpha);
            *(float2*)&C[m * N + n]       = v0;
            *(float2*)&C[(m + 8) * N + n] = v1;
        }
    }
}

// ---------------- elementwise helpers ---------------------------------------
__device__ __forceinline__ void split2(float x, __nv_bfloat16& h, __nv_bfloat16& l) {
    h = __float2bfloat16(x);
    l = __float2bfloat16(x - __bfloat162float(h));
}

// fp32 [R x 2048] -> bf16 [R x 4096] hi|lo
__global__ void __launch_bounds__(256)
convert_split(const float* __restrict__ in, __nv_bfloat16* __restrict__ out)
{
    size_t idx = (size_t)blockIdx.x * 256 + threadIdx.x;
    size_t r = idx >> 11; int c = (int)(idx & 2047);
    __nv_bfloat16 h, l; split2(in[idx], h, l);
    out[(r << 12) + c] = h;
    out[(r << 12) + 2048 + c] = l;
}

// rope + split; optional fp32 output
__global__ void __launch_bounds__(256)
rope_split(const float* __restrict__ x, float* __restrict__ out32,
           __nv_bfloat16* __restrict__ out2,
           const float* __restrict__ cosb, const float* __restrict__ sinb)
{
    size_t idx = (size_t)blockIdx.x * 256 + threadIdx.x;  // B*S*D2
    int i = (int)(idx & (D2c - 1));
    size_t bs = idx >> 10;
    int s = (int)(bs & (Ss - 1));
    size_t b32 = bs * Hh, b2 = bs * 2 * Hh;
    float c  = cosb[(size_t)s * D2c + i];
    float sn = sinb[(size_t)s * D2c + i];
    float xr = x[b32 + i], xi = x[b32 + D2c + i];
    float orr = xr * c - xi * sn;
    float oii = xr * sn + xi * c;
    if (out32) { out32[b32 + 2 * i] = orr; out32[b32 + 2 * i + 1] = oii; }
    __nv_bfloat16 h0, l0, h1, l1;
    split2(orr, h0, l0); split2(oii, h1, l1);
    out2[b2 + 2 * i]          = h0;
    out2[b2 + 2 * i + 1]      = h1;
    out2[b2 + Hh + 2 * i]     = l0;
    out2[b2 + Hh + 2 * i + 1] = l1;
}

// v [b][4096][2048] -> vt2 [b][2048][2*4096] (hi|lo)
__global__ void transpose_split(const float* __restrict__ v, __nv_bfloat16* __restrict__ vt2)
{
    __shared__ float t[32][33];
    int b = blockIdx.z;
    int n0 = blockIdx.x * 32, k0 = blockIdx.y * 32;
    const float* vb = v + (size_t)b * Ss * Hh;
    __nv_bfloat16* ob = vt2 + (size_t)b * Hh * 2 * Ss;
    int tx = threadIdx.x, ty0 = threadIdx.y;
    #pragma unroll
    for (int r = 0; r < 4; ++r) {
        int ty = ty0 + r * 8;
        t[ty][tx] = vb[(size_t)(k0 + ty) * Hh + n0 + tx];
    }
    __syncthreads();
    #pragma unroll
    for (int r = 0; r < 4; ++r) {
        int ty = ty0 + r * 8;
        __nv_bfloat16 h, l; split2(t[tx][ty], h, l);
        size_t o = (size_t)(n0 + ty) * (2 * Ss) + k0 + tx;
        ob[o] = h; ob[o + Ss] = l;
    }
}

// softmax over rows of 4096 + emit bf16 hi|lo [row][2*4096]
__global__ void __launch_bounds__(256)
softmax_split(const float* __restrict__ P, __nv_bfloat16* __restrict__ P2)
{
    const float* row = P + (size_t)blockIdx.x * Ss;
    __nv_bfloat16* orow = P2 + (size_t)blockIdx.x * (2 * Ss);
    int tid = threadIdx.x;
    float e[16];
    __shared__ float red[256];
    float m = -INFINITY;
    #pragma unroll
    for (int j = 0; j < 16; ++j) { e[j] = row[tid + j * 256]; m = fmaxf(m, e[j]); }
    red[tid] = m; __syncthreads();
    for (int s = 128; s > 0; s >>= 1) {
        if (tid < s) red[tid] = fmaxf(red[tid], red[tid + s]);
        __syncthreads();
    }
    m = red[0]; __syncthreads();
    float sum = 0.f;
    #pragma unroll
    for (int j = 0; j < 16; ++j) { e[j] = __expf(e[j] - m); sum += e[j]; }
    red[tid] = sum; __syncthreads();
    for (int s = 128; s > 0; s >>= 1) {
        if (tid < s) red[tid] += red[tid + s];
        __syncthreads();
    }
    float inv = 1.f / red[0];
    #pragma unroll
    for (int j = 0; j < 16; ++j) {
        __nv_bfloat16 h, l; split2(e[j] * inv, h, l);
        orow[tid + j * 256] = h;
        orow[Ss + tid + j * 256] = l;
    }
}

// ---------------- launch ----------------------------------------------------
extern "C" void kernel_launch(void* const* d_in, const int* in_sizes, int n_in,
                              void* d_out, int out_size)
{
    const float* hs   = (const float*)d_in[0];
    const float* wq   = (const float*)d_in[1];
    const float* wk   = (const float*)d_in[2];
    const float* wv   = (const float*)d_in[3];
    const float* wo   = (const float*)d_in[4];
    const float* fcos = (const float*)d_in[5];
    const float* fsin = (const float*)d_in[6];

    float* out = (float*)d_out;
    const long long T = (long long)Bb * Ss * Hh;
    float* out_o = out;
    float* out_k = out + T;
    float* out_v = out + 2 * T;

    float *q, *k, *p, *ctx;
    __nv_bfloat16 *hs2, *wq2, *wk2, *wv2, *wo2, *qr2, *kr2, *p2, *vt2, *ctx2;
    cudaGetSymbolAddress((void**)&q,    g_q);
    cudaGetSymbolAddress((void**)&k,    g_k);
    cudaGetSymbolAddress((void**)&p,    g_p);
    cudaGetSymbolAddress((void**)&ctx,  g_ctx);
    cudaGetSymbolAddress((void**)&hs2,  g_hs2);
    cudaGetSymbolAddress((void**)&wq2,  g_wq2);
    cudaGetSymbolAddress((void**)&wk2,  g_wk2);
    cudaGetSymbolAddress((void**)&wv2,  g_wv2);
    cudaGetSymbolAddress((void**)&wo2,  g_wo2);
    cudaGetSymbolAddress((void**)&qr2,  g_qr2);
    cudaGetSymbolAddress((void**)&kr2,  g_kr2);
    cudaGetSymbolAddress((void**)&p2,   g_p2);
    cudaGetSymbolAddress((void**)&vt2,  g_vt2);
    cudaGetSymbolAddress((void**)&ctx2, g_ctx2);

    cudaFuncSetAttribute(gemm3p, cudaFuncAttributeMaxDynamicSharedMemorySize, GSMEM);

    dim3 blk(256);
    // split inputs to bf16 hi/lo
    convert_split<<<(unsigned)((size_t)Bb*Ss*Hh/256), blk>>>(hs, hs2);
    convert_split<<<(unsigned)((size_t)Hh*Hh/256), blk>>>(wq, wq2);
    convert_split<<<(unsigned)((size_t)Hh*Hh/256), blk>>>(wk, wk2);
    convert_split<<<(unsigned)((size_t)Hh*Hh/256), blk>>>(wv, wv2);
    convert_split<<<(unsigned)((size_t)Hh*Hh/256), blk>>>(wo, wo2);

    // projections
    dim3 gproj(Hh / BN, (Bb * Ss) / BM, 1);
    gemm3p<<<gproj, 256, GSMEM>>>(hs2, wq2, q,     Bb*Ss, Hh, Hh, 0, 0, 0, 1.f);
    gemm3p<<<gproj, 256, GSMEM>>>(hs2, wk2, k,     Bb*Ss, Hh, Hh, 0, 0, 0, 1.f);
    gemm3p<<<gproj, 256, GSMEM>>>(hs2, wv2, out_v, Bb*Ss, Hh, Hh, 0, 0, 0, 1.f);

    // rope + split
    unsigned grope = (unsigned)((size_t)Bb * Ss * D2c / 256);
    rope_split<<<grope, blk>>>(q, nullptr, qr2, fcos, fsin);
    rope_split<<<grope, blk>>>(k, out_k,   kr2, fcos, fsin);

    // v transpose+split
    dim3 gtr(Hh / 32, Ss / 32, Bb);
    transpose_split<<<gtr, dim3(32, 8)>>>(out_v, vt2);

    // scores = 0.125 * Qr @ Kr^T (per batch)
    dim3 gsc(Ss / BN, Ss / BM, Bb);
    gemm3p<<<gsc, 256, GSMEM>>>(qr2, kr2, p, Ss, Ss, Hh,
                                (long long)Ss*2*Hh, (long long)Ss*2*Hh,
                                (long long)Ss*Ss, SCALEF);

    // softmax + split
    softmax_split<<<Bb * Ss, blk>>>(p, p2);

    // ctx = P @ V (per batch)
    dim3 gcx(Hh / BN, Ss / BM, Bb);
    gemm3p<<<gcx, 256, GSMEM>>>(p2, vt2, ctx, Ss, Hh, Ss,
                                (long long)Ss*2*Ss, (long long)Hh*2*Ss,
                                (long long)Ss*Hh, 1.f);

    // output projection
    convert_split<<<(unsigned)((size_t)Bb*Ss*Hh/256), blk>>>(ctx, ctx2);
    gemm3p<<<gproj, 256, GSMEM>>>(ctx2, wo2, out_o, Bb*Ss, Hh, Hh, 0, 0, 0, 1.f);
}

// round 5
// speedup vs baseline: 2.4946x; 1.2900x over previous
#include <cuda_runtime.h>
#include <cuda_bf16.h>
#include <math.h>
#include <stdint.h>

#define Bb 2
#define Ss 4096
#define Hh 2048
#define D2c 1024
#define SCALEF 0.125f

// ---------------- static device scratch (allocation-free rule) --------------
__device__ __align__(256) float g_q  [(size_t)Bb*Ss*Hh];
__device__ __align__(256) float g_k  [(size_t)Bb*Ss*Hh];
__device__ __align__(256) float g_p  [(size_t)Bb*Ss*Ss];
__device__ __align__(256) float g_ctx[(size_t)Bb*Ss*Hh];
__device__ __align__(256) __nv_bfloat16 g_hs2 [(size_t)Bb*Ss*2*Hh];
__device__ __align__(256) __nv_bfloat16 g_wq2 [(size_t)Hh*2*Hh];
__device__ __align__(256) __nv_bfloat16 g_wk2 [(size_t)Hh*2*Hh];
__device__ __align__(256) __nv_bfloat16 g_wv2 [(size_t)Hh*2*Hh];
__device__ __align__(256) __nv_bfloat16 g_wo2 [(size_t)Hh*2*Hh];
__device__ __align__(256) __nv_bfloat16 g_qr2 [(size_t)Bb*Ss*2*Hh];
__device__ __align__(256) __nv_bfloat16 g_kr2 [(size_t)Bb*Ss*2*Hh];
__device__ __align__(256) __nv_bfloat16 g_p2  [(size_t)Bb*Ss*2*Ss];
__device__ __align__(256) __nv_bfloat16 g_vt2 [(size_t)Bb*Hh*2*Ss];
__device__ __align__(256) __nv_bfloat16 g_ctx2[(size_t)Bb*Ss*2*Hh];

// ---------------- PTX helpers (portable: sm_80+ only) -----------------------
__device__ __forceinline__ uint32_t smem_u32(const void* p) {
    uint32_t a;
    asm("{ .reg .u64 t; cvta.to.shared.u64 t, %1; cvt.u32.u64 %0, t; }" : "=r"(a) : "l"(p));
    return a;
}
__device__ __forceinline__ void cp_async16(uint32_t dst, const void* src) {
    asm volatile("cp.async.cg.shared.global [%0], [%1], 16;" :: "r"(dst), "l"(src) : "memory");
}
#define CP_COMMIT() asm volatile("cp.async.commit_group;" ::: "memory")
#define CP_WAIT1()  asm volatile("cp.async.wait_group 1;" ::: "memory")
#define CP_WAIT0()  asm volatile("cp.async.wait_group 0;" ::: "memory")

__device__ __forceinline__ void ldsm_x4(uint32_t& r0, uint32_t& r1, uint32_t& r2, uint32_t& r3,
                                        uint32_t addr) {
    asm volatile("ldmatrix.sync.aligned.m8n8.x4.shared.b16 {%0,%1,%2,%3}, [%4];"
                 : "=r"(r0), "=r"(r1), "=r"(r2), "=r"(r3) : "r"(addr));
}
__device__ __forceinline__ void mma16816(float& d0, float& d1, float& d2, float& d3,
                                         uint32_t a0, uint32_t a1, uint32_t a2, uint32_t a3,
                                         uint32_t b0, uint32_t b1) {
    asm volatile("mma.sync.aligned.m16n8k16.row.col.f32.bf16.bf16.f32 "
                 "{%0,%1,%2,%3}, {%4,%5,%6,%7}, {%8,%9}, {%0,%1,%2,%3};"
                 : "+f"(d0), "+f"(d1), "+f"(d2), "+f"(d3)
                 : "r"(a0), "r"(a1), "r"(a2), "r"(a3), "r"(b0), "r"(b1));
}
__device__ __forceinline__ uint32_t swz(uint32_t b) { return b ^ ((b >> 3) & 0x70); }

// ---------------- mma.sync bf16 3-pass GEMM ---------------------------------
// C = alpha * (Ahi*Bhi + Alo*Bhi + Ahi*Blo)
// A2: [M x 2K] bf16 row-major (hi cols [0,K), lo [K,2K)). B2: [N x 2K] same.
// CTA tile 128x256, 8 warps in 2x4, warp tile 64x64. One CTA per SM.
#define BM 128
#define BN 256
#define BK 64
#define STAGES 3
#define ATILE (BM * BK * 2)            // 16384 B
#define BTILE (BN * BK * 2)            // 32768 B
#define STAGE_BYTES (ATILE + BTILE)    // 49152 B
#define GSMEM (STAGES * STAGE_BYTES)   // 147456 B

__device__ __forceinline__ void load_chunk(
    const __nv_bfloat16* __restrict__ A2, const __nv_bfloat16* __restrict__ B2,
    uint32_t sb, int c, int kchunks, int K, long long K2, int m0, int n0, int tid)
{
    int pass = c / kchunks;
    int kk = c - pass * kchunks;
    int aoff = kk * BK + (pass == 1 ? K : 0);
    int boff = kk * BK + (pass == 2 ? K : 0);
    uint32_t bufA = sb + (uint32_t)(c % STAGES) * STAGE_BYTES;
    uint32_t bufB = bufA + ATILE;
    #pragma unroll
    for (int j = 0; j < 4; ++j) {
        int lin = tid + j * 256;
        int row = lin >> 3, ch = lin & 7;
        cp_async16(bufA + swz(row * 128 + ch * 16),
                   A2 + (long long)(m0 + row) * K2 + aoff + ch * 8);
    }
    #pragma unroll
    for (int j = 0; j < 8; ++j) {
        int lin = tid + j * 256;
        int row = lin >> 3, ch = lin & 7;
        cp_async16(bufB + swz(row * 128 + ch * 16),
                   B2 + (long long)(n0 + row) * K2 + boff + ch * 8);
    }
}

__global__ void __launch_bounds__(256, 1)
gemm3p(const __nv_bfloat16* __restrict__ A2, const __nv_bfloat16* __restrict__ B2,
       float* __restrict__ C, int M, int N, int K,
       long long sA, long long sB, long long sC, float alpha)
{
    extern __shared__ char smem[];
    uint32_t sb = smem_u32(smem);
    const int tid = threadIdx.x;
    const int wid = tid >> 5, lane = tid & 31;
    const int wm = wid & 1;      // 2 warps along M: 64 rows each
    const int wn = wid >> 1;     // 4 warps along N: 64 cols each
    A2 += (long long)blockIdx.z * sA;
    B2 += (long long)blockIdx.z * sB;
    C  += (long long)blockIdx.z * sC;
    const int m0 = blockIdx.y * BM, n0 = blockIdx.x * BN;
    const long long K2 = 2LL * K;
    const int kchunks = K / BK, nchunks = 3 * kchunks;

    float acc[4][8][4];
    #pragma unroll
    for (int i = 0; i < 4; ++i)
        #pragma unroll
        for (int j = 0; j < 8; ++j)
            #pragma unroll
            for (int q = 0; q < 4; ++q) acc[i][j][q] = 0.f;

    const int lrow = lane & 15;
    const int lhalf = lane >> 4;

    load_chunk(A2, B2, sb, 0, kchunks, K, K2, m0, n0, tid); CP_COMMIT();
    load_chunk(A2, B2, sb, 1, kchunks, K, K2, m0, n0, tid); CP_COMMIT();

    for (int c = 0; c < nchunks; ++c) {
        if (c + 1 < nchunks) { CP_WAIT1(); } else { CP_WAIT0(); }
        __syncthreads();
        if (c + 2 < nchunks) {
            load_chunk(A2, B2, sb, c + 2, kchunks, K, K2, m0, n0, tid);
            CP_COMMIT();
        }
        uint32_t aBase = sb + (uint32_t)(c % STAGES) * STAGE_BYTES;
        uint32_t bBase = aBase + ATILE;
        #pragma unroll
        for (int ks = 0; ks < BK / 16; ++ks) {
            uint32_t a[4][4], b[8][2];
            int ch = ks * 2 + lhalf;
            #pragma unroll
            for (int im = 0; im < 4; ++im) {
                int row = wm * 64 + im * 16 + lrow;
                ldsm_x4(a[im][0], a[im][1], a[im][2], a[im][3],
                        aBase + row * 128 + ((ch ^ (row & 7)) * 16));
            }
            #pragma unroll
            for (int ib = 0; ib < 4; ++ib) {
                int row = wn * 64 + ib * 16 + lrow;
                ldsm_x4(b[2*ib][0], b[2*ib+1][0], b[2*ib][1], b[2*ib+1][1],
                        bBase + row * 128 + ((ch ^ (row & 7)) * 16));
            }
            #pragma unroll
            for (int im = 0; im < 4; ++im)
                #pragma unroll
                for (int in = 0; in < 8; ++in)
                    mma16816(acc[im][in][0], acc[im][in][1], acc[im][in][2], acc[im][in][3],
                             a[im][0], a[im][1], a[im][2], a[im][3],
                             b[in][0], b[in][1]);
        }
    }
    __syncthreads();

    const int r0 = lane >> 2;
    const int cc = (lane & 3) * 2;
    #pragma unroll
    for (int im = 0; im < 4; ++im) {
        #pragma unroll
        for (int in = 0; in < 8; ++in) {
            long long m = m0 + wm * 64 + im * 16 + r0;
            long long n = n0 + wn * 64 + in * 8 + cc;
            float2 v0 = make_float2(acc[im][in][0] * alpha, acc[im][in][1] * alpha);
            float2 v1 = make_float2(acc[im][in][2] * alpha, acc[im][in][3] * alpha);
            *(float2*)&C[m * N + n]       = v0;
            *(float2*)&C[(m + 8) * N + n] = v1;
        }
    }
}

// ---------------- elementwise helpers ---------------------------------------
__device__ __forceinline__ void split2(float x, __nv_bfloat16& h, __nv_bfloat16& l) {
    h = __float2bfloat16(x);
    l = __float2bfloat16(x - __bfloat162float(h));
}

// fp32 [R x 2048] -> bf16 [R x 4096] hi|lo
__global__ void __launch_bounds__(256)
convert_split(const float* __restrict__ in, __nv_bfloat16* __restrict__ out)
{
    size_t idx = (size_t)blockIdx.x * 256 + threadIdx.x;
    size_t r = idx >> 11; int c = (int)(idx & 2047);
    __nv_bfloat16 h, l; split2(in[idx], h, l);
    out[(r << 12) + c] = h;
    out[(r << 12) + 2048 + c] = l;
}

// rope + split; optional fp32 output
__global__ void __launch_bounds__(256)
rope_split(const float* __restrict__ x, float* __restrict__ out32,
           __nv_bfloat16* __restrict__ out2,
           const float* __restrict__ cosb, const float* __restrict__ sinb)
{
    size_t idx = (size_t)blockIdx.x * 256 + threadIdx.x;  // B*S*D2
    int i = (int)(idx & (D2c - 1));
    size_t bs = idx >> 10;
    int s = (int)(bs & (Ss - 1));
    size_t b32 = bs * Hh, b2 = bs * 2 * Hh;
    float c  = cosb[(size_t)s * D2c + i];
    float sn = sinb[(size_t)s * D2c + i];
    float xr = x[b32 + i], xi = x[b32 + D2c + i];
    float orr = xr * c - xi * sn;
    float oii = xr * sn + xi * c;
    if (out32) { out32[b32 + 2 * i] = orr; out32[b32 + 2 * i + 1] = oii; }
    __nv_bfloat16 h0, l0, h1, l1;
    split2(orr, h0, l0); split2(oii, h1, l1);
    out2[b2 + 2 * i]          = h0;
    out2[b2 + 2 * i + 1]      = h1;
    out2[b2 + Hh + 2 * i]     = l0;
    out2[b2 + Hh + 2 * i + 1] = l1;
}

// v [b][4096][2048] -> vt2 [b][2048][2*4096] (hi|lo)
__global__ void transpose_split(const float* __restrict__ v, __nv_bfloat16* __restrict__ vt2)
{
    __shared__ float t[32][33];
    int b = blockIdx.z;
    int n0 = blockIdx.x * 32, k0 = blockIdx.y * 32;
    const float* vb = v + (size_t)b * Ss * Hh;
    __nv_bfloat16* ob = vt2 + (size_t)b * Hh * 2 * Ss;
    int tx = threadIdx.x, ty0 = threadIdx.y;
    #pragma unroll
    for (int r = 0; r < 4; ++r) {
        int ty = ty0 + r * 8;
        t[ty][tx] = vb[(size_t)(k0 + ty) * Hh + n0 + tx];
    }
    __syncthreads();
    #pragma unroll
    for (int r = 0; r < 4; ++r) {
        int ty = ty0 + r * 8;
        __nv_bfloat16 h, l; split2(t[tx][ty], h, l);
        size_t o = (size_t)(n0 + ty) * (2 * Ss) + k0 + tx;
        ob[o] = h; ob[o + Ss] = l;
    }
}

// softmax over rows of 4096 + emit bf16 hi|lo [row][2*4096]
__global__ void __launch_bounds__(256)
softmax_split(const float* __restrict__ P, __nv_bfloat16* __restrict__ P2)
{
    const float* row = P + (size_t)blockIdx.x * Ss;
    __nv_bfloat16* orow = P2 + (size_t)blockIdx.x * (2 * Ss);
    int tid = threadIdx.x;
    float e[16];
    __shared__ float red[256];
    float m = -INFINITY;
    #pragma unroll
    for (int j = 0; j < 16; ++j) { e[j] = row[tid + j * 256]; m = fmaxf(m, e[j]); }
    red[tid] = m; __syncthreads();
    for (int s = 128; s > 0; s >>= 1) {
        if (tid < s) red[tid] = fmaxf(red[tid], red[tid + s]);
        __syncthreads();
    }
    m = red[0]; __syncthreads();
    float sum = 0.f;
    #pragma unroll
    for (int j = 0; j < 16; ++j) { e[j] = __expf(e[j] - m); sum += e[j]; }
    red[tid] = sum; __syncthreads();
    for (int s = 128; s > 0; s >>= 1) {
        if (tid < s) red[tid] += red[tid + s];
        __syncthreads();
    }
    float inv = 1.f / red[0];
    #pragma unroll
    for (int j = 0; j < 16; ++j) {
        __nv_bfloat16 h, l; split2(e[j] * inv, h, l);
        orow[tid + j * 256] = h;
        orow[Ss + tid + j * 256] = l;
    }
}

// ---------------- launch ----------------------------------------------------
extern "C" void kernel_launch(void* const* d_in, const int* in_sizes, int n_in,
                              void* d_out, int out_size)
{
    const float* hs   = (const float*)d_in[0];
    const float* wq   = (const float*)d_in[1];
    const float* wk   = (const float*)d_in[2];
    const float* wv   = (const float*)d_in[3];
    const float* wo   = (const float*)d_in[4];
    const float* fcos = (const float*)d_in[5];
    const float* fsin = (const float*)d_in[6];

    float* out = (float*)d_out;
    const long long T = (long long)Bb * Ss * Hh;
    float* out_o = out;
    float* out_k = out + T;
    float* out_v = out + 2 * T;

    float *q, *k, *p, *ctx;
    __nv_bfloat16 *hs2, *wq2, *wk2, *wv2, *wo2, *qr2, *kr2, *p2, *vt2, *ctx2;
    cudaGetSymbolAddress((void**)&q,    g_q);
    cudaGetSymbolAddress((void**)&k,    g_k);
    cudaGetSymbolAddress((void**)&p,    g_p);
    cudaGetSymbolAddress((void**)&ctx,  g_ctx);
    cudaGetSymbolAddress((void**)&hs2,  g_hs2);
    cudaGetSymbolAddress((void**)&wq2,  g_wq2);
    cudaGetSymbolAddress((void**)&wk2,  g_wk2);
    cudaGetSymbolAddress((void**)&wv2,  g_wv2);
    cudaGetSymbolAddress((void**)&wo2,  g_wo2);
    cudaGetSymbolAddress((void**)&qr2,  g_qr2);
    cudaGetSymbolAddress((void**)&kr2,  g_kr2);
    cudaGetSymbolAddress((void**)&p2,   g_p2);
    cudaGetSymbolAddress((void**)&vt2,  g_vt2);
    cudaGetSymbolAddress((void**)&ctx2, g_ctx2);

    cudaFuncSetAttribute(gemm3p, cudaFuncAttributeMaxDynamicSharedMemorySize, GSMEM);

    dim3 blk(256);
    // split inputs to bf16 hi/lo
    convert_split<<<(unsigned)((size_t)Bb*Ss*Hh/256), blk>>>(hs, hs2);
    convert_split<<<(unsigned)((size_t)Hh*Hh/256), blk>>>(wq, wq2);
    convert_split<<<(unsigned)((size_t)Hh*Hh/256), blk>>>(wk, wk2);
    convert_split<<<(unsigned)((size_t)Hh*Hh/256), blk>>>(wv, wv2);
    convert_split<<<(unsigned)((size_t)Hh*Hh/256), blk>>>(wo, wo2);

    // projections
    dim3 gproj(Hh / BN, (Bb * Ss) / BM, 1);
    gemm3p<<<gproj, 256, GSMEM>>>(hs2, wq2, q,     Bb*Ss, Hh, Hh, 0, 0, 0, 1.f);
    gemm3p<<<gproj, 256, GSMEM>>>(hs2, wk2, k,     Bb*Ss, Hh, Hh, 0, 0, 0, 1.f);
    gemm3p<<<gproj, 256, GSMEM>>>(hs2, wv2, out_v, Bb*Ss, Hh, Hh, 0, 0, 0, 1.f);

    // rope + split
    unsigned grope = (unsigned)((size_t)Bb * Ss * D2c / 256);
    rope_split<<<grope, blk>>>(q, nullptr, qr2, fcos, fsin);
    rope_split<<<grope, blk>>>(k, out_k,   kr2, fcos, fsin);

    // v transpose+split
    dim3 gtr(Hh / 32, Ss / 32, Bb);
    transpose_split<<<gtr, dim3(32, 8)>>>(out_v, vt2);

    // scores = 0.125 * Qr @ Kr^T (per batch)
    dim3 gsc(Ss / BN, Ss / BM, Bb);
    gemm3p<<<gsc, 256, GSMEM>>>(qr2, kr2, p, Ss, Ss, Hh,
                                (long long)Ss*2*Hh, (long long)Ss*2*Hh,
                                (long long)Ss*Ss, SCALEF);

    // softmax + split
    softmax_split<<<Bb * Ss, blk>>>(p, p2);

    // ctx = P @ V (per batch)
    dim3 gcx(Hh / BN, Ss / BM, Bb);
    gemm3p<<<gcx, 256, GSMEM>>>(p2, vt2, ctx, Ss, Hh, Ss,
                                (long long)Ss*2*Ss, (long long)Hh*2*Ss,
                                (long long)Ss*Hh, 1.f);

    // output projection
    convert_split<<<(unsigned)((size_t)Bb*Ss*Hh/256), blk>>>(ctx, ctx2);
    gemm3p<<<gproj, 256, GSMEM>>>(ctx2, wo2, out_o, Bb*Ss, Hh, Hh, 0, 0, 0, 1.f);
}

// round 6
// speedup vs baseline: 2.8418x; 1.1392x over previous
#include <cuda_runtime.h>
#include <cuda_bf16.h>
#include <math.h>
#include <stdint.h>

#define Bb 2
#define Ss 4096
#define Hh 2048
#define D2c 1024
#define SCALEF 0.125f

// ---------------- static device scratch (allocation-free rule) --------------
__device__ __align__(256) float g_q  [(size_t)Bb*Ss*Hh];
__device__ __align__(256) float g_k  [(size_t)Bb*Ss*Hh];
__device__ __align__(256) float g_p  [(size_t)Bb*Ss*Ss];
__device__ __align__(256) float g_ctx[(size_t)Bb*Ss*Hh];
__device__ __align__(256) __nv_bfloat16 g_hs2 [(size_t)Bb*Ss*2*Hh];
__device__ __align__(256) __nv_bfloat16 g_wq2 [(size_t)Hh*2*Hh];
__device__ __align__(256) __nv_bfloat16 g_wk2 [(size_t)Hh*2*Hh];
__device__ __align__(256) __nv_bfloat16 g_wv2 [(size_t)Hh*2*Hh];
__device__ __align__(256) __nv_bfloat16 g_wo2 [(size_t)Hh*2*Hh];
__device__ __align__(256) __nv_bfloat16 g_qr2 [(size_t)Bb*Ss*2*Hh];
__device__ __align__(256) __nv_bfloat16 g_kr2 [(size_t)Bb*Ss*2*Hh];
__device__ __align__(256) __nv_bfloat16 g_p2  [(size_t)Bb*Ss*2*Ss];
__device__ __align__(256) __nv_bfloat16 g_vt2 [(size_t)Bb*Hh*2*Ss];
__device__ __align__(256) __nv_bfloat16 g_ctx2[(size_t)Bb*Ss*2*Hh];

// ---------------- PTX helpers (portable: sm_80+ only) -----------------------
__device__ __forceinline__ uint32_t smem_u32(const void* p) {
    uint32_t a;
    asm("{ .reg .u64 t; cvta.to.shared.u64 t, %1; cvt.u32.u64 %0, t; }" : "=r"(a) : "l"(p));
    return a;
}
__device__ __forceinline__ void cp_async16(uint32_t dst, const void* src) {
    asm volatile("cp.async.cg.shared.global [%0], [%1], 16;" :: "r"(dst), "l"(src) : "memory");
}
#define CP_COMMIT() asm volatile("cp.async.commit_group;" ::: "memory")
#define CP_WAIT1()  asm volatile("cp.async.wait_group 1;" ::: "memory")
#define CP_WAIT0()  asm volatile("cp.async.wait_group 0;" ::: "memory")

__device__ __forceinline__ void ldsm_x4(uint32_t& r0, uint32_t& r1, uint32_t& r2, uint32_t& r3,
                                        uint32_t addr) {
    asm volatile("ldmatrix.sync.aligned.m8n8.x4.shared.b16 {%0,%1,%2,%3}, [%4];"
                 : "=r"(r0), "=r"(r1), "=r"(r2), "=r"(r3) : "r"(addr));
}
__device__ __forceinline__ void mma16816(float& d0, float& d1, float& d2, float& d3,
                                         uint32_t a0, uint32_t a1, uint32_t a2, uint32_t a3,
                                         uint32_t b0, uint32_t b1) {
    asm volatile("mma.sync.aligned.m16n8k16.row.col.f32.bf16.bf16.f32 "
                 "{%0,%1,%2,%3}, {%4,%5,%6,%7}, {%8,%9}, {%0,%1,%2,%3};"
                 : "+f"(d0), "+f"(d1), "+f"(d2), "+f"(d3)
                 : "r"(a0), "r"(a1), "r"(a2), "r"(a3), "r"(b0), "r"(b1));
}
__device__ __forceinline__ uint32_t swz(uint32_t b) { return b ^ ((b >> 3) & 0x70); }

// ---------------- mma.sync bf16 fused-3-product GEMM ------------------------
// C = alpha * (Ahi*Bhi + Alo*Bhi + Ahi*Blo)
// A2: [M x 2K] bf16 row-major (hi cols [0,K), lo [K,2K)). B2: [N x 2K] same.
// Stage row layout (128 B): [hi 32 bf16 | lo 32 bf16] -> SW128 swizzle intact.
// CTA tile 128x128xBK32 per chunk, 4 warps 2x2, warp tile 64x64, 2 CTAs/SM.
#define BM 128
#define BN 128
#define BK 32
#define STAGES 3
#define ATILE (BM * 128)               // 16384 B (hi|lo packed per row)
#define STAGE_BYTES (2 * ATILE)        // 32768 B
#define GSMEM (STAGES * STAGE_BYTES)   // 98304 B

__device__ __forceinline__ void load_chunk(
    const __nv_bfloat16* __restrict__ A2, const __nv_bfloat16* __restrict__ B2,
    uint32_t sb, int c, int K, long long K2, int m0, int n0, int tid)
{
    int k0 = c * BK;
    uint32_t bufA = sb + (uint32_t)(c % STAGES) * STAGE_BYTES;
    uint32_t bufB = bufA + ATILE;
    #pragma unroll
    for (int j = 0; j < 8; ++j) {
        int lin = tid + j * 128;          // 0..1023
        int row = lin >> 3, ch = lin & 7; // ch<4: hi, ch>=4: lo
        long long col = (ch < 4) ? (k0 + ch * 8) : ((long long)K + k0 + (ch - 4) * 8);
        cp_async16(bufA + swz(row * 128 + ch * 16),
                   A2 + (long long)(m0 + row) * K2 + col);
    }
    #pragma unroll
    for (int j = 0; j < 8; ++j) {
        int lin = tid + j * 128;
        int row = lin >> 3, ch = lin & 7;
        long long col = (ch < 4) ? (k0 + ch * 8) : ((long long)K + k0 + (ch - 4) * 8);
        cp_async16(bufB + swz(row * 128 + ch * 16),
                   B2 + (long long)(n0 + row) * K2 + col);
    }
}

__global__ void __launch_bounds__(128, 2)
gemm3f(const __nv_bfloat16* __restrict__ A2, const __nv_bfloat16* __restrict__ B2,
       float* __restrict__ C, int M, int N, int K,
       long long sA, long long sB, long long sC, float alpha)
{
    extern __shared__ char smem[];
    uint32_t sb = smem_u32(smem);
    const int tid = threadIdx.x;
    const int wid = tid >> 5, lane = tid & 31;
    const int wm = wid & 1;      // 2 warps along M: 64 rows each
    const int wn = wid >> 1;     // 2 warps along N: 64 cols each
    A2 += (long long)blockIdx.z * sA;
    B2 += (long long)blockIdx.z * sB;
    C  += (long long)blockIdx.z * sC;
    const int m0 = blockIdx.y * BM, n0 = blockIdx.x * BN;
    const long long K2 = 2LL * K;
    const int nchunks = K / BK;

    float acc[4][8][4];
    #pragma unroll
    for (int i = 0; i < 4; ++i)
        #pragma unroll
        for (int j = 0; j < 8; ++j)
            #pragma unroll
            for (int q = 0; q < 4; ++q) acc[i][j][q] = 0.f;

    const int lrow = lane & 15;
    const int lhalf = lane >> 4;

    load_chunk(A2, B2, sb, 0, K, K2, m0, n0, tid); CP_COMMIT();
    load_chunk(A2, B2, sb, 1, K, K2, m0, n0, tid); CP_COMMIT();

    for (int c = 0; c < nchunks; ++c) {
        if (c + 1 < nchunks) { CP_WAIT1(); } else { CP_WAIT0(); }
        __syncthreads();
        if (c + 2 < nchunks) {
            load_chunk(A2, B2, sb, c + 2, K, K2, m0, n0, tid);
            CP_COMMIT();
        }
        uint32_t aBase = sb + (uint32_t)(c % STAGES) * STAGE_BYTES;
        uint32_t bBase = aBase + ATILE;
        #pragma unroll
        for (int ks = 0; ks < BK / 16; ++ks) {
            int chh = ks * 2 + lhalf;       // hi halves: 0..3
            int chl = 4 + ks * 2 + lhalf;   // lo halves: 4..7
            uint32_t ah[4][4], al[4][4], bh[8][2], bl[8][2];
            #pragma unroll
            for (int im = 0; im < 4; ++im) {
                int row = wm * 64 + im * 16 + lrow;
                uint32_t rb = aBase + row * 128;
                int sx = row & 7;
                ldsm_x4(ah[im][0], ah[im][1], ah[im][2], ah[im][3], rb + ((chh ^ sx) * 16));
                ldsm_x4(al[im][0], al[im][1], al[im][2], al[im][3], rb + ((chl ^ sx) * 16));
            }
            #pragma unroll
            for (int ib = 0; ib < 4; ++ib) {
                int row = wn * 64 + ib * 16 + lrow;
                uint32_t rb = bBase + row * 128;
                int sx = row & 7;
                ldsm_x4(bh[2*ib][0], bh[2*ib+1][0], bh[2*ib][1], bh[2*ib+1][1], rb + ((chh ^ sx) * 16));
                ldsm_x4(bl[2*ib][0], bl[2*ib+1][0], bl[2*ib][1], bl[2*ib+1][1], rb + ((chl ^ sx) * 16));
            }
            #pragma unroll
            for (int im = 0; im < 4; ++im)
                #pragma unroll
                for (int in = 0; in < 8; ++in) {
                    mma16816(acc[im][in][0], acc[im][in][1], acc[im][in][2], acc[im][in][3],
                             ah[im][0], ah[im][1], ah[im][2], ah[im][3],
                             bh[in][0], bh[in][1]);
                    mma16816(acc[im][in][0], acc[im][in][1], acc[im][in][2], acc[im][in][3],
                             al[im][0], al[im][1], al[im][2], al[im][3],
                             bh[in][0], bh[in][1]);
                    mma16816(acc[im][in][0], acc[im][in][1], acc[im][in][2], acc[im][in][3],
                             ah[im][0], ah[im][1], ah[im][2], ah[im][3],
                             bl[in][0], bl[in][1]);
                }
        }
    }
    __syncthreads();

    const int r0 = lane >> 2;
    const int cc = (lane & 3) * 2;
    #pragma unroll
    for (int im = 0; im < 4; ++im) {
        #pragma unroll
        for (int in = 0; in < 8; ++in) {
            long long m = m0 + wm * 64 + im * 16 + r0;
            long long n = n0 + wn * 64 + in * 8 + cc;
            float2 v0 = make_float2(acc[im][in][0] * alpha, acc[im][in][1] * alpha);
            float2 v1 = make_float2(acc[im][in][2] * alpha, acc[im][in][3] * alpha);
            *(float2*)&C[m * N + n]       = v0;
            *(float2*)&C[(m + 8) * N + n] = v1;
        }
    }
}

// ---------------- elementwise helpers ---------------------------------------
__device__ __forceinline__ void split2(float x, __nv_bfloat16& h, __nv_bfloat16& l) {
    h = __float2bfloat16(x);
    l = __float2bfloat16(x - __bfloat162float(h));
}

// fp32 [R x 2048] -> bf16 [R x 4096] hi|lo
__global__ void __launch_bounds__(256)
convert_split(const float* __restrict__ in, __nv_bfloat16* __restrict__ out)
{
    size_t idx = (size_t)blockIdx.x * 256 + threadIdx.x;
    size_t r = idx >> 11; int c = (int)(idx & 2047);
    __nv_bfloat16 h, l; split2(in[idx], h, l);
    out[(r << 12) + c] = h;
    out[(r << 12) + 2048 + c] = l;
}

// rope + split; optional fp32 output
__global__ void __launch_bounds__(256)
rope_split(const float* __restrict__ x, float* __restrict__ out32,
           __nv_bfloat16* __restrict__ out2,
           const float* __restrict__ cosb, const float* __restrict__ sinb)
{
    size_t idx = (size_t)blockIdx.x * 256 + threadIdx.x;  // B*S*D2
    int i = (int)(idx & (D2c - 1));
    size_t bs = idx >> 10;
    int s = (int)(bs & (Ss - 1));
    size_t b32 = bs * Hh, b2 = bs * 2 * Hh;
    float c  = cosb[(size_t)s * D2c + i];
    float sn = sinb[(size_t)s * D2c + i];
    float xr = x[b32 + i], xi = x[b32 + D2c + i];
    float orr = xr * c - xi * sn;
    float oii = xr * sn + xi * c;
    if (out32) { out32[b32 + 2 * i] = orr; out32[b32 + 2 * i + 1] = oii; }
    __nv_bfloat16 h0, l0, h1, l1;
    split2(orr, h0, l0); split2(oii, h1, l1);
    out2[b2 + 2 * i]          = h0;
    out2[b2 + 2 * i + 1]      = h1;
    out2[b2 + Hh + 2 * i]     = l0;
    out2[b2 + Hh + 2 * i + 1] = l1;
}

// v [b][4096][2048] -> vt2 [b][2048][2*4096] (hi|lo)
__global__ void transpose_split(const float* __restrict__ v, __nv_bfloat16* __restrict__ vt2)
{
    __shared__ float t[32][33];
    int b = blockIdx.z;
    int n0 = blockIdx.x * 32, k0 = blockIdx.y * 32;
    const float* vb = v + (size_t)b * Ss * Hh;
    __nv_bfloat16* ob = vt2 + (size_t)b * Hh * 2 * Ss;
    int tx = threadIdx.x, ty0 = threadIdx.y;
    #pragma unroll
    for (int r = 0; r < 4; ++r) {
        int ty = ty0 + r * 8;
        t[ty][tx] = vb[(size_t)(k0 + ty) * Hh + n0 + tx];
    }
    __syncthreads();
    #pragma unroll
    for (int r = 0; r < 4; ++r) {
        int ty = ty0 + r * 8;
        __nv_bfloat16 h, l; split2(t[tx][ty], h, l);
        size_t o = (size_t)(n0 + ty) * (2 * Ss) + k0 + tx;
        ob[o] = h; ob[o + Ss] = l;
    }
}

// softmax over rows of 4096 + emit bf16 hi|lo [row][2*4096]
__global__ void __launch_bounds__(256)
softmax_split(const float* __restrict__ P, __nv_bfloat16* __restrict__ P2)
{
    const float* row = P + (size_t)blockIdx.x * Ss;
    __nv_bfloat16* orow = P2 + (size_t)blockIdx.x * (2 * Ss);
    int tid = threadIdx.x;
    float e[16];
    __shared__ float red[256];
    float m = -INFINITY;
    #pragma unroll
    for (int j = 0; j < 16; ++j) { e[j] = row[tid + j * 256]; m = fmaxf(m, e[j]); }
    red[tid] = m; __syncthreads();
    for (int s = 128; s > 0; s >>= 1) {
        if (tid < s) red[tid] = fmaxf(red[tid], red[tid + s]);
        __syncthreads();
    }
    m = red[0]; __syncthreads();
    float sum = 0.f;
    #pragma unroll
    for (int j = 0; j < 16; ++j) { e[j] = __expf(e[j] - m); sum += e[j]; }
    red[tid] = sum; __syncthreads();
    for (int s = 128; s > 0; s >>= 1) {
        if (tid < s) red[tid] += red[tid + s];
        __syncthreads();
    }
    float inv = 1.f / red[0];
    #pragma unroll
    for (int j = 0; j < 16; ++j) {
        __nv_bfloat16 h, l; split2(e[j] * inv, h, l);
        orow[tid + j * 256] = h;
        orow[Ss + tid + j * 256] = l;
    }
}

// ---------------- launch ----------------------------------------------------
extern "C" void kernel_launch(void* const* d_in, const int* in_sizes, int n_in,
                              void* d_out, int out_size)
{
    const float* hs   = (const float*)d_in[0];
    const float* wq   = (const float*)d_in[1];
    const float* wk   = (const float*)d_in[2];
    const float* wv   = (const float*)d_in[3];
    const float* wo   = (const float*)d_in[4];
    const float* fcos = (const float*)d_in[5];
    const float* fsin = (const float*)d_in[6];

    float* out = (float*)d_out;
    const long long T = (long long)Bb * Ss * Hh;
    float* out_o = out;
    float* out_k = out + T;
    float* out_v = out + 2 * T;

    float *q, *k, *p, *ctx;
    __nv_bfloat16 *hs2, *wq2, *wk2, *wv2, *wo2, *qr2, *kr2, *p2, *vt2, *ctx2;
    cudaGetSymbolAddress((void**)&q,    g_q);
    cudaGetSymbolAddress((void**)&k,    g_k);
    cudaGetSymbolAddress((void**)&p,    g_p);
    cudaGetSymbolAddress((void**)&ctx,  g_ctx);
    cudaGetSymbolAddress((void**)&hs2,  g_hs2);
    cudaGetSymbolAddress((void**)&wq2,  g_wq2);
    cudaGetSymbolAddress((void**)&wk2,  g_wk2);
    cudaGetSymbolAddress((void**)&wv2,  g_wv2);
    cudaGetSymbolAddress((void**)&wo2,  g_wo2);
    cudaGetSymbolAddress((void**)&qr2,  g_qr2);
    cudaGetSymbolAddress((void**)&kr2,  g_kr2);
    cudaGetSymbolAddress((void**)&p2,   g_p2);
    cudaGetSymbolAddress((void**)&vt2,  g_vt2);
    cudaGetSymbolAddress((void**)&ctx2, g_ctx2);

    cudaFuncSetAttribute(gemm3f, cudaFuncAttributeMaxDynamicSharedMemorySize, GSMEM);

    dim3 blk(256);
    // split inputs to bf16 hi/lo
    convert_split<<<(unsigned)((size_t)Bb*Ss*Hh/256), blk>>>(hs, hs2);
    convert_split<<<(unsigned)((size_t)Hh*Hh/256), blk>>>(wq, wq2);
    convert_split<<<(unsigned)((size_t)Hh*Hh/256), blk>>>(wk, wk2);
    convert_split<<<(unsigned)((size_t)Hh*Hh/256), blk>>>(wv, wv2);
    convert_split<<<(unsigned)((size_t)Hh*Hh/256), blk>>>(wo, wo2);

    // projections
    dim3 gproj(Hh / BN, (Bb * Ss) / BM, 1);
    gemm3f<<<gproj, 128, GSMEM>>>(hs2, wq2, q,     Bb*Ss, Hh, Hh, 0, 0, 0, 1.f);
    gemm3f<<<gproj, 128, GSMEM>>>(hs2, wk2, k,     Bb*Ss, Hh, Hh, 0, 0, 0, 1.f);
    gemm3f<<<gproj, 128, GSMEM>>>(hs2, wv2, out_v, Bb*Ss, Hh, Hh, 0, 0, 0, 1.f);

    // rope + split
    unsigned grope = (unsigned)((size_t)Bb * Ss * D2c / 256);
    rope_split<<<grope, blk>>>(q, nullptr, qr2, fcos, fsin);
    rope_split<<<grope, blk>>>(k, out_k,   kr2, fcos, fsin);

    // v transpose+split
    dim3 gtr(Hh / 32, Ss / 32, Bb);
    transpose_split<<<gtr, dim3(32, 8)>>>(out_v, vt2);

    // scores = 0.125 * Qr @ Kr^T (per batch)
    dim3 gsc(Ss / BN, Ss / BM, Bb);
    gemm3f<<<gsc, 128, GSMEM>>>(qr2, kr2, p, Ss, Ss, Hh,
                                (long long)Ss*2*Hh, (long long)Ss*2*Hh,
                                (long long)Ss*Ss, SCALEF);

    // softmax + split
    softmax_split<<<Bb * Ss, blk>>>(p, p2);

    // ctx = P @ V (per batch)
    dim3 gcx(Hh / BN, Ss / BM, Bb);
    gemm3f<<<gcx, 128, GSMEM>>>(p2, vt2, ctx, Ss, Hh, Ss,
                                (long long)Ss*2*Ss, (long long)Hh*2*Ss,
                                (long long)Ss*Hh, 1.f);

    // output projection
    convert_split<<<(unsigned)((size_t)Bb*Ss*Hh/256), blk>>>(ctx, ctx2);
    gemm3f<<<gproj, 128, GSMEM>>>(ctx2, wo2, out_o, Bb*Ss, Hh, Hh, 0, 0, 0, 1.f);
}

// round 8
// speedup vs baseline: 2.9135x; 1.0252x over previous
#include <cuda_runtime.h>
#include <cuda_bf16.h>
#include <math.h>
#include <stdint.h>

#define Bb 2
#define Ss 4096
#define Hh 2048
#define D2c 1024
#define SCALEF 0.125f

// ---------------- static device scratch (allocation-free rule) --------------
__device__ __align__(256) float g_p  [(size_t)Bb*Ss*Ss];
__device__ __align__(256) __nv_bfloat16 g_hs2 [(size_t)Bb*Ss*2*Hh];
__device__ __align__(256) __nv_bfloat16 g_wq2 [(size_t)Hh*2*Hh];
__device__ __align__(256) __nv_bfloat16 g_wk2 [(size_t)Hh*2*Hh];
__device__ __align__(256) __nv_bfloat16 g_wv2 [(size_t)Hh*2*Hh];
__device__ __align__(256) __nv_bfloat16 g_wo2 [(size_t)Hh*2*Hh];
__device__ __align__(256) __nv_bfloat16 g_qr2 [(size_t)Bb*Ss*2*Hh];
__device__ __align__(256) __nv_bfloat16 g_kr2 [(size_t)Bb*Ss*2*Hh];
__device__ __align__(256) __nv_bfloat16 g_p2  [(size_t)Bb*Ss*2*Ss];
__device__ __align__(256) __nv_bfloat16 g_vt2 [(size_t)Bb*Hh*2*Ss];
__device__ __align__(256) __nv_bfloat16 g_ctx2[(size_t)Bb*Ss*2*Hh];

// ---------------- PTX helpers (portable: sm_80+ only) -----------------------
__device__ __forceinline__ uint32_t smem_u32(const void* p) {
    uint32_t a;
    asm("{ .reg .u64 t; cvta.to.shared.u64 t, %1; cvt.u32.u64 %0, t; }" : "=r"(a) : "l"(p));
    return a;
}
__device__ __forceinline__ void cp_async16(uint32_t dst, const void* src) {
    asm volatile("cp.async.cg.shared.global [%0], [%1], 16;" :: "r"(dst), "l"(src) : "memory");
}
#define CP_COMMIT() asm volatile("cp.async.commit_group;" ::: "memory")
#define CP_WAIT1()  asm volatile("cp.async.wait_group 1;" ::: "memory")
#define CP_WAIT0()  asm volatile("cp.async.wait_group 0;" ::: "memory")

__device__ __forceinline__ void ldsm_x4(uint32_t& r0, uint32_t& r1, uint32_t& r2, uint32_t& r3,
                                        uint32_t addr) {
    asm volatile("ldmatrix.sync.aligned.m8n8.x4.shared.b16 {%0,%1,%2,%3}, [%4];"
                 : "=r"(r0), "=r"(r1), "=r"(r2), "=r"(r3) : "r"(addr));
}
__device__ __forceinline__ void mma16816(float& d0, float& d1, float& d2, float& d3,
                                         uint32_t a0, uint32_t a1, uint32_t a2, uint32_t a3,
                                         uint32_t b0, uint32_t b1) {
    asm volatile("mma.sync.aligned.m16n8k16.row.col.f32.bf16.bf16.f32 "
                 "{%0,%1,%2,%3}, {%4,%5,%6,%7}, {%8,%9}, {%0,%1,%2,%3};"
                 : "+f"(d0), "+f"(d1), "+f"(d2), "+f"(d3)
                 : "r"(a0), "r"(a1), "r"(a2), "r"(a3), "r"(b0), "r"(b1));
}
__device__ __forceinline__ uint32_t swz(uint32_t b) { return b ^ ((b >> 3) & 0x70); }

__device__ __forceinline__ void split2(float x, __nv_bfloat16& h, __nv_bfloat16& l) {
    h = __float2bfloat16(x);
    l = __float2bfloat16(x - __bfloat162float(h));
}
__device__ __forceinline__ uint32_t pack2(__nv_bfloat16 a, __nv_bfloat16 b) {
    __nv_bfloat162 v(a, b);
    return *reinterpret_cast<uint32_t*>(&v);
}

// ---------------- mma.sync bf16 fused-3-product GEMM ------------------------
// C = alpha * (Ahi*Bhi + Alo*Bhi + Ahi*Blo)
// A2: [M x 2K] bf16 (hi cols [0,K), lo [K,2K)). B2: [N x 2K] same.
// Stage row (128 B): [hi 32 bf16 | lo 32 bf16], SW128 swizzle.
// CTA 128x128xBK32, 4 warps 2x2, warp tile 64x64, 2 CTAs/SM.
// EPI: 0 = plain fp32 C; 1 = RoPE (pairs) -> optional fp32 C + split to C2;
//      2 = split only -> C2 (batch-offset by sC in C2 elements).
#define BM 128
#define BN 128
#define BK 32
#define STAGES 3
#define ATILE (BM * 128)
#define STAGE_BYTES (2 * ATILE)
#define GSMEM (STAGES * STAGE_BYTES)   // 98304 B

__device__ __forceinline__ void load_chunk(
    const __nv_bfloat16* __restrict__ A2, const __nv_bfloat16* __restrict__ B2,
    uint32_t sb, int c, int K, long long K2, int m0, int n0, int tid)
{
    int k0 = c * BK;
    uint32_t bufA = sb + (uint32_t)(c % STAGES) * STAGE_BYTES;
    uint32_t bufB = bufA + ATILE;
    #pragma unroll
    for (int j = 0; j < 8; ++j) {
        int lin = tid + j * 128;
        int row = lin >> 3, ch = lin & 7;
        long long col = (ch < 4) ? (k0 + ch * 8) : ((long long)K + k0 + (ch - 4) * 8);
        cp_async16(bufA + swz(row * 128 + ch * 16),
                   A2 + (long long)(m0 + row) * K2 + col);
    }
    #pragma unroll
    for (int j = 0; j < 8; ++j) {
        int lin = tid + j * 128;
        int row = lin >> 3, ch = lin & 7;
        long long col = (ch < 4) ? (k0 + ch * 8) : ((long long)K + k0 + (ch - 4) * 8);
        cp_async16(bufB + swz(row * 128 + ch * 16),
                   B2 + (long long)(n0 + row) * K2 + col);
    }
}

template<int EPI>
__global__ void __launch_bounds__(128, 2)
gemm3f(const __nv_bfloat16* __restrict__ A2, const __nv_bfloat16* __restrict__ B2,
       float* __restrict__ C, __nv_bfloat16* __restrict__ C2,
       const float* __restrict__ cosb, const float* __restrict__ sinb,
       int M, int N, int K,
       long long sA, long long sB, long long sC, float alpha)
{
    extern __shared__ char smem[];
    uint32_t sb = smem_u32(smem);
    const int tid = threadIdx.x;
    const int wid = tid >> 5, lane = tid & 31;
    const int wm = wid & 1;
    const int wn = wid >> 1;
    A2 += (long long)blockIdx.z * sA;
    B2 += (long long)blockIdx.z * sB;
    if (EPI == 0) C += (long long)blockIdx.z * sC;
    if (EPI == 2) C2 += (long long)blockIdx.z * sC;   // batch offset for split output
    const int m0 = blockIdx.y * BM, n0 = blockIdx.x * BN;
    const long long K2 = 2LL * K;
    const int nchunks = K / BK;

    float acc[4][8][4];
    #pragma unroll
    for (int i = 0; i < 4; ++i)
        #pragma unroll
        for (int j = 0; j < 8; ++j)
            #pragma unroll
            for (int q = 0; q < 4; ++q) acc[i][j][q] = 0.f;

    const int lrow = lane & 15;
    const int lhalf = lane >> 4;

    load_chunk(A2, B2, sb, 0, K, K2, m0, n0, tid); CP_COMMIT();
    load_chunk(A2, B2, sb, 1, K, K2, m0, n0, tid); CP_COMMIT();

    for (int c = 0; c < nchunks; ++c) {
        if (c + 1 < nchunks) { CP_WAIT1(); } else { CP_WAIT0(); }
        __syncthreads();
        if (c + 2 < nchunks) {
            load_chunk(A2, B2, sb, c + 2, K, K2, m0, n0, tid);
            CP_COMMIT();
        }
        uint32_t aBase = sb + (uint32_t)(c % STAGES) * STAGE_BYTES;
        uint32_t bBase = aBase + ATILE;
        #pragma unroll
        for (int ks = 0; ks < BK / 16; ++ks) {
            int chh = ks * 2 + lhalf;
            int chl = 4 + ks * 2 + lhalf;
            uint32_t ah[4][4], al[4][4], bh[8][2], bl[8][2];
            #pragma unroll
            for (int im = 0; im < 4; ++im) {
                int row = wm * 64 + im * 16 + lrow;
                uint32_t rb = aBase + row * 128;
                int sx = row & 7;
                ldsm_x4(ah[im][0], ah[im][1], ah[im][2], ah[im][3], rb + ((chh ^ sx) * 16));
                ldsm_x4(al[im][0], al[im][1], al[im][2], al[im][3], rb + ((chl ^ sx) * 16));
            }
            #pragma unroll
            for (int ib = 0; ib < 4; ++ib) {
                int row = wn * 64 + ib * 16 + lrow;
                uint32_t rb = bBase + row * 128;
                int sx = row & 7;
                ldsm_x4(bh[2*ib][0], bh[2*ib+1][0], bh[2*ib][1], bh[2*ib+1][1], rb + ((chh ^ sx) * 16));
                ldsm_x4(bl[2*ib][0], bl[2*ib+1][0], bl[2*ib][1], bl[2*ib+1][1], rb + ((chl ^ sx) * 16));
            }
            // product-major ordering: long reuse distance on each accumulator
            #pragma unroll
            for (int im = 0; im < 4; ++im)
                #pragma unroll
                for (int in = 0; in < 8; ++in)
                    mma16816(acc[im][in][0], acc[im][in][1], acc[im][in][2], acc[im][in][3],
                             ah[im][0], ah[im][1], ah[im][2], ah[im][3], bh[in][0], bh[in][1]);
            #pragma unroll
            for (int im = 0; im < 4; ++im)
                #pragma unroll
                for (int in = 0; in < 8; ++in)
                    mma16816(acc[im][in][0], acc[im][in][1], acc[im][in][2], acc[im][in][3],
                             al[im][0], al[im][1], al[im][2], al[im][3], bh[in][0], bh[in][1]);
            #pragma unroll
            for (int im = 0; im < 4; ++im)
                #pragma unroll
                for (int in = 0; in < 8; ++in)
                    mma16816(acc[im][in][0], acc[im][in][1], acc[im][in][2], acc[im][in][3],
                             ah[im][0], ah[im][1], ah[im][2], ah[im][3], bl[in][0], bl[in][1]);
        }
    }
    __syncthreads();

    const int r0 = lane >> 2;
    const int cc = (lane & 3) * 2;
    const long long N2 = 2LL * N;
    #pragma unroll
    for (int im = 0; im < 4; ++im) {
        #pragma unroll
        for (int in = 0; in < 8; ++in) {
            long long m = m0 + wm * 64 + im * 16 + r0;
            long long n = n0 + wn * 64 + in * 8 + cc;
            float v0 = acc[im][in][0] * alpha, v1 = acc[im][in][1] * alpha;
            float v2 = acc[im][in][2] * alpha, v3 = acc[im][in][3] * alpha;
            if (EPI == 0) {
                *(float2*)&C[m * N + n]       = make_float2(v0, v1);
                *(float2*)&C[(m + 8) * N + n] = make_float2(v2, v3);
            } else if (EPI == 1) {
                int i = (int)(n >> 1);
                int s1 = (int)(m & (Ss - 1));
                int s2 = (int)((m + 8) & (Ss - 1));
                float c1 = cosb[(size_t)s1 * D2c + i], sn1 = sinb[(size_t)s1 * D2c + i];
                float c2 = cosb[(size_t)s2 * D2c + i], sn2 = sinb[(size_t)s2 * D2c + i];
                float o0 = v0 * c1 - v1 * sn1, o1 = v0 * sn1 + v1 * c1;
                float o2 = v2 * c2 - v3 * sn2, o3 = v2 * sn2 + v3 * c2;
                if (C) {
                    *(float2*)&C[m * N + n]       = make_float2(o0, o1);
                    *(float2*)&C[(m + 8) * N + n] = make_float2(o2, o3);
                }
                __nv_bfloat16 h0,l0,h1,l1,h2,l2,h3,l3;
                split2(o0,h0,l0); split2(o1,h1,l1); split2(o2,h2,l2); split2(o3,h3,l3);
                uint32_t* c2p = (uint32_t*)C2;
                c2p[(m * N2 + n) >> 1]           = pack2(h0, h1);
                c2p[(m * N2 + N + n) >> 1]       = pack2(l0, l1);
                c2p[((m + 8) * N2 + n) >> 1]     = pack2(h2, h3);
                c2p[((m + 8) * N2 + N + n) >> 1] = pack2(l2, l3);
            } else { // EPI == 2: split only
                __nv_bfloat16 h0,l0,h1,l1,h2,l2,h3,l3;
                split2(v0,h0,l0); split2(v1,h1,l1); split2(v2,h2,l2); split2(v3,h3,l3);
                uint32_t* c2p = (uint32_t*)C2;
                c2p[(m * N2 + n) >> 1]           = pack2(h0, h1);
                c2p[(m * N2 + N + n) >> 1]       = pack2(l0, l1);
                c2p[((m + 8) * N2 + n) >> 1]     = pack2(h2, h3);
                c2p[((m + 8) * N2 + N + n) >> 1] = pack2(l2, l3);
            }
        }
    }
}

// ---------------- elementwise kernels ----------------------------------------
// fp32 [R x 2048] -> bf16 [R x 4096] hi|lo, float4 vectorized
__global__ void __launch_bounds__(256)
convert_split4(const float* __restrict__ in, __nv_bfloat16* __restrict__ out)
{
    size_t idx = (size_t)blockIdx.x * 256 + threadIdx.x;   // one per 4 elems
    size_t r = idx >> 9; int c4 = (int)(idx & 511);
    float4 v = *(const float4*)&in[(r << 11) + c4 * 4];
    __nv_bfloat16 h0,l0,h1,l1,h2,l2,h3,l3;
    split2(v.x,h0,l0); split2(v.y,h1,l1); split2(v.z,h2,l2); split2(v.w,h3,l3);
    uint2 hv = make_uint2(pack2(h0,h1), pack2(h2,h3));
    uint2 lv = make_uint2(pack2(l0,l1), pack2(l2,l3));
    *(uint2*)&out[(r << 12) + c4 * 4]        = hv;
    *(uint2*)&out[(r << 12) + 2048 + c4 * 4] = lv;
}

// weight convert with row permutation: out row j <- in row (j odd ? 1024+j/2 : j/2)
__global__ void __launch_bounds__(256)
convert_split_perm(const float* __restrict__ in, __nv_bfloat16* __restrict__ out)
{
    size_t idx = (size_t)blockIdx.x * 256 + threadIdx.x;
    size_t j = idx >> 9; int c4 = (int)(idx & 511);
    size_t pj = (j & 1) ? (1024 + (j >> 1)) : (j >> 1);
    float4 v = *(const float4*)&in[(pj << 11) + c4 * 4];
    __nv_bfloat16 h0,l0,h1,l1,h2,l2,h3,l3;
    split2(v.x,h0,l0); split2(v.y,h1,l1); split2(v.z,h2,l2); split2(v.w,h3,l3);
    uint2 hv = make_uint2(pack2(h0,h1), pack2(h2,h3));
    uint2 lv = make_uint2(pack2(l0,l1), pack2(l2,l3));
    *(uint2*)&out[(j << 12) + c4 * 4]        = hv;
    *(uint2*)&out[(j << 12) + 2048 + c4 * 4] = lv;
}

// v [b][4096][2048] -> vt2 [b][2048][2*4096] (hi|lo)
__global__ void transpose_split(const float* __restrict__ v, __nv_bfloat16* __restrict__ vt2)
{
    __shared__ float t[32][33];
    int b = blockIdx.z;
    int n0 = blockIdx.x * 32, k0 = blockIdx.y * 32;
    const float* vb = v + (size_t)b * Ss * Hh;
    __nv_bfloat16* ob = vt2 + (size_t)b * Hh * 2 * Ss;
    int tx = threadIdx.x, ty0 = threadIdx.y;
    #pragma unroll
    for (int r = 0; r < 4; ++r) {
        int ty = ty0 + r * 8;
        t[ty][tx] = vb[(size_t)(k0 + ty) * Hh + n0 + tx];
    }
    __syncthreads();
    #pragma unroll
    for (int r = 0; r < 4; ++r) {
        int ty = ty0 + r * 8;
        __nv_bfloat16 h, l; split2(t[tx][ty], h, l);
        size_t o = (size_t)(n0 + ty) * (2 * Ss) + k0 + tx;
        ob[o] = h; ob[o + Ss] = l;
    }
}

// softmax over rows of 4096 + emit bf16 hi|lo [row][2*4096]; contiguous/thread
__global__ void __launch_bounds__(256)
softmax_split(const float* __restrict__ P, __nv_bfloat16* __restrict__ P2)
{
    const float* row = P + (size_t)blockIdx.x * Ss;
    __nv_bfloat16* orow = P2 + (size_t)blockIdx.x * (2 * Ss);
    int tid = threadIdx.x;
    float e[16];
    __shared__ float red[256];
    float m = -INFINITY;
    #pragma unroll
    for (int j4 = 0; j4 < 4; ++j4) {
        float4 v = *(const float4*)&row[tid * 16 + j4 * 4];
        e[j4*4+0]=v.x; e[j4*4+1]=v.y; e[j4*4+2]=v.z; e[j4*4+3]=v.w;
        m = fmaxf(m, fmaxf(fmaxf(v.x, v.y), fmaxf(v.z, v.w)));
    }
    red[tid] = m; __syncthreads();
    for (int s = 128; s > 0; s >>= 1) {
        if (tid < s) red[tid] = fmaxf(red[tid], red[tid + s]);
        __syncthreads();
    }
    m = red[0]; __syncthreads();
    float sum = 0.f;
    #pragma unroll
    for (int j = 0; j < 16; ++j) { e[j] = __expf(e[j] - m); sum += e[j]; }
    red[tid] = sum; __syncthreads();
    for (int s = 128; s > 0; s >>= 1) {
        if (tid < s) red[tid] += red[tid + s];
        __syncthreads();
    }
    float inv = 1.f / red[0];
    __nv_bfloat16 h[16], l[16];
    #pragma unroll
    for (int j = 0; j < 16; ++j) split2(e[j] * inv, h[j], l[j]);
    uint4 hv0 = make_uint4(pack2(h[0],h[1]), pack2(h[2],h[3]), pack2(h[4],h[5]), pack2(h[6],h[7]));
    uint4 hv1 = make_uint4(pack2(h[8],h[9]), pack2(h[10],h[11]), pack2(h[12],h[13]), pack2(h[14],h[15]));
    uint4 lv0 = make_uint4(pack2(l[0],l[1]), pack2(l[2],l[3]), pack2(l[4],l[5]), pack2(l[6],l[7]));
    uint4 lv1 = make_uint4(pack2(l[8],l[9]), pack2(l[10],l[11]), pack2(l[12],l[13]), pack2(l[14],l[15]));
    *(uint4*)&orow[tid * 16]          = hv0;
    *(uint4*)&orow[tid * 16 + 8]      = hv1;
    *(uint4*)&orow[Ss + tid * 16]     = lv0;
    *(uint4*)&orow[Ss + tid * 16 + 8] = lv1;
}

// ---------------- launch ----------------------------------------------------
extern "C" void kernel_launch(void* const* d_in, const int* in_sizes, int n_in,
                              void* d_out, int out_size)
{
    const float* hs   = (const float*)d_in[0];
    const float* wq   = (const float*)d_in[1];
    const float* wk   = (const float*)d_in[2];
    const float* wv   = (const float*)d_in[3];
    const float* wo   = (const float*)d_in[4];
    const float* fcos = (const float*)d_in[5];
    const float* fsin = (const float*)d_in[6];

    float* out = (float*)d_out;
    const long long T = (long long)Bb * Ss * Hh;
    float* out_o = out;
    float* out_k = out + T;
    float* out_v = out + 2 * T;

    float *p;
    __nv_bfloat16 *hs2, *wq2, *wk2, *wv2, *wo2, *qr2, *kr2, *p2, *vt2, *ctx2;
    cudaGetSymbolAddress((void**)&p,    g_p);
    cudaGetSymbolAddress((void**)&hs2,  g_hs2);
    cudaGetSymbolAddress((void**)&wq2,  g_wq2);
    cudaGetSymbolAddress((void**)&wk2,  g_wk2);
    cudaGetSymbolAddress((void**)&wv2,  g_wv2);
    cudaGetSymbolAddress((void**)&wo2,  g_wo2);
    cudaGetSymbolAddress((void**)&qr2,  g_qr2);
    cudaGetSymbolAddress((void**)&kr2,  g_kr2);
    cudaGetSymbolAddress((void**)&p2,   g_p2);
    cudaGetSymbolAddress((void**)&vt2,  g_vt2);
    cudaGetSymbolAddress((void**)&ctx2, g_ctx2);

    cudaFuncSetAttribute(gemm3f<0>, cudaFuncAttributeMaxDynamicSharedMemorySize, GSMEM);
    cudaFuncSetAttribute(gemm3f<1>, cudaFuncAttributeMaxDynamicSharedMemorySize, GSMEM);
    cudaFuncSetAttribute(gemm3f<2>, cudaFuncAttributeMaxDynamicSharedMemorySize, GSMEM);

    dim3 blk(256);
    // splits: hs plain; wq/wk permuted (for fused RoPE); wv/wo plain
    convert_split4<<<(unsigned)((size_t)Bb*Ss*Hh/1024), blk>>>(hs, hs2);
    convert_split_perm<<<(unsigned)((size_t)Hh*Hh/1024), blk>>>(wq, wq2);
    convert_split_perm<<<(unsigned)((size_t)Hh*Hh/1024), blk>>>(wk, wk2);
    convert_split4<<<(unsigned)((size_t)Hh*Hh/1024), blk>>>(wv, wv2);
    convert_split4<<<(unsigned)((size_t)Hh*Hh/1024), blk>>>(wo, wo2);

    // projections: q/k with fused RoPE epilogue (permuted weights), v plain
    dim3 gproj(Hh / BN, (Bb * Ss) / BM, 1);
    gemm3f<1><<<gproj, 128, GSMEM>>>(hs2, wq2, nullptr, qr2, fcos, fsin,
                                     Bb*Ss, Hh, Hh, 0, 0, 0, 1.f);
    gemm3f<1><<<gproj, 128, GSMEM>>>(hs2, wk2, out_k, kr2, fcos, fsin,
                                     Bb*Ss, Hh, Hh, 0, 0, 0, 1.f);
    gemm3f<0><<<gproj, 128, GSMEM>>>(hs2, wv2, out_v, nullptr, nullptr, nullptr,
                                     Bb*Ss, Hh, Hh, 0, 0, 0, 1.f);

    // v transpose+split
    dim3 gtr(Hh / 32, Ss / 32, Bb);
    transpose_split<<<gtr, dim3(32, 8)>>>(out_v, vt2);

    // scores = 0.125 * Qr @ Kr^T (per batch)
    dim3 gsc(Ss / BN, Ss / BM, Bb);
    gemm3f<0><<<gsc, 128, GSMEM>>>(qr2, kr2, p, nullptr, nullptr, nullptr,
                                   Ss, Ss, Hh,
                                   (long long)Ss*2*Hh, (long long)Ss*2*Hh,
                                   (long long)Ss*Ss, SCALEF);

    // softmax + split
    softmax_split<<<Bb * Ss, blk>>>(p, p2);

    // ctx = P @ V (per batch), split fused into epilogue -> ctx2 (batch stride in C2 elems)
    dim3 gcx(Hh / BN, Ss / BM, Bb);
    gemm3f<2><<<gcx, 128, GSMEM>>>(p2, vt2, nullptr, ctx2, nullptr, nullptr,
                                   Ss, Hh, Ss,
                                   (long long)Ss*2*Ss, (long long)Hh*2*Ss,
                                   (long long)Ss*2*Hh, 1.f);

    // output projection
    gemm3f<0><<<gproj, 128, GSMEM>>>(ctx2, wo2, out_o, nullptr, nullptr, nullptr,
                                     Bb*Ss, Hh, Hh, 0, 0, 0, 1.f);
}